// round 5
// baseline (speedup 1.0000x reference)
#include <cuda_runtime.h>
#include <math.h>

#define BB    64
#define NPTS  2048
#define SDIR  512
#define NDIRS 1536
#define QQ    1024
#define T0D   286
#define T1D   165
#define T2D   84
#define NSH   36
#define SK    8

// exp(-d2/SIGMA2) with SIGMA2 = 0.08 -> 1/SIGMA2 = 12.5
// C1 = 12.5 * log2(e), C2 = 2*C1
#define C1F 18.0336880111120430f
#define C2F 36.0673760222240860f

__constant__ int c_pidx[36] = {
    0, 2, 5, 8, 12, 17, 22, 27, 32,
    38, 45, 52, 59, 66, 73, 80,
    88, 97, 106, 115, 124, 133, 142, 151, 160,
    170, 181, 192, 203, 214, 225, 236, 247, 258, 269, 280};
__constant__ float c_radii[3] = {0.4f, 0.8f, 1.2f};

// ---------------- scratch (static device globals; no allocation) ----------------
__device__ float4 g_xp[BB * NPTS];
__device__ float  g_f[BB * NDIRS];
__device__ float  g_sh[BB * NSH * 3];
__device__ float  g_E0[QQ * NSH];
__device__ float  g_rs0[QQ];
__device__ float  g_z0[BB * NSH * 16];
__device__ float  g_Y[BB * QQ * 64];
__device__ float  g_z1[BB * T1D * 32];
__device__ float  g_z2[BB * T2D * 64];
__device__ float  g_t3[BB * T2D * 64];
__device__ float  g_ck[SK * BB * T2D * 64];   // split-K partials (max layer)
__device__ float  g_part[2 * 1024 * 64];      // BN partials (sum | sumsq)
__device__ float  g_scale[64];
__device__ float  g_shift[64];
__device__ float  g_a1[BB * 512];
__device__ float  g_a2[BB * 256];

__device__ __forceinline__ float ex2(float x) {
    float y;
    asm("ex2.approx.ftz.f32 %0, %1;" : "=f"(y) : "f"(x));
    return y;
}

// ---------------- merged prep: points premultiply + E0 gather/rowsum ----------------
__global__ void k_prep_e0(const float* __restrict__ x, const float* __restrict__ D0) {
    if (blockIdx.x < 512) {
        int i = blockIdx.x * 256 + threadIdx.x;
        float a = x[3 * i], b = x[3 * i + 1], c = x[3 * i + 2];
        float n2 = a * a + b * b + c * c;
        g_xp[i] = make_float4(a * C2F, b * C2F, c * C2F, -C1F * n2);
    } else {
        int q = (blockIdx.x - 512) * 256 + threadIdx.x;
        if (q < QQ) {
            const float* row = D0 + q * T0D;
            float s = 0.f;
            for (int t = 0; t < T0D; t++) s += row[t];
            g_rs0[q] = s;
            for (int j = 0; j < NSH; j++) g_E0[q * NSH + j] = row[c_pidx[j]];
        }
    }
}

// ---------------- shell densities ----------------
__global__ void __launch_bounds__(256) k_shell(const float* __restrict__ dirs) {
    __shared__ float4 sp[NPTS];  // 32 KB
    int b = blockIdx.y;
    int s = blockIdx.x * 256 + threadIdx.x;
    const float4* src = g_xp + b * NPTS;
    for (int i = threadIdx.x; i < NPTS; i += 256) sp[i] = src[i];
    __syncthreads();

    int shell = s >> 9;
    int j = s & 511;
    float r = c_radii[shell];
    const float* d = dirs + (size_t)(shell * SDIR + j) * 3;
    float cx = d[0] * r, cy = d[1] * r, cz = d[2] * r;
    float acc0 = 0.f, acc1 = 0.f;
#pragma unroll 8
    for (int i = 0; i < NPTS; i += 2) {
        float4 p = sp[i];
        float4 q = sp[i + 1];
        float t0 = fmaf(p.x, cx, fmaf(p.y, cy, fmaf(p.z, cz, p.w)));
        float t1 = fmaf(q.x, cx, fmaf(q.y, cy, fmaf(q.z, cz, q.w)));
        acc0 += ex2(t0);
        acc1 += ex2(t1);
    }
    float sc = ex2(-C1F * r * r) * (1.0f / (float)NPTS);
    g_f[b * NDIRS + s] = (acc0 + acc1) * sc;
}

// ---------------- SH projection, warp-per-output ----------------
__global__ void k_shproj(const float* __restrict__ A_sh) {
    int w = blockIdx.x * 8 + (threadIdx.x >> 5);
    int l = threadIdx.x & 31;
    int b = w / 108;
    int o = w % 108;
    int shell = o / NSH;
    int j = o % NSH;
    const float* arow = A_sh + j * SDIR;
    const float* f = g_f + b * NDIRS + shell * SDIR;
    float acc = 0.f;
#pragma unroll
    for (int s = l; s < SDIR; s += 32) acc = fmaf(arow[s], f[s], acc);
#pragma unroll
    for (int st = 16; st > 0; st >>= 1)
        acc += __shfl_xor_sync(0xffffffffu, acc, st);
    if (l == 0) g_sh[(b * NSH + j) * 3 + shell] = acc;
}

// ---------------- channel mix (layer-0 only) ----------------
__global__ void k_mix(const float* __restrict__ in, const float* __restrict__ W,
                      float* __restrict__ out, int T, int Cin, int U) {
    int i = blockIdx.x * 256 + threadIdx.x;
    if (i >= BB * T * U) return;
    int u = i % U;
    int bt = i / U;
    const float* row = in + (size_t)bt * Cin;
    float acc = 0.f;
    for (int c = 0; c < Cin; c++) acc = fmaf(row[c], W[c * U + u], acc);
    out[i] = acc;
}

// ---------------- 2D register-tiled GEMM (split-K + fused BN-stats capable) ----------------
// C[z][bb][m][u] = sum_{k slice z} A[m][k] * act(B[bb][k][u]) (+ rowsum[m]*bias[u])
// Block 256 threads (16x16); each thread RM x 4 outputs. Tile M = 16*RM, NE = N*NB = 64.
template <int N, int NB, int RM>
__global__ void __launch_bounds__(256) k_gemm2(
    const float* __restrict__ A, const float* __restrict__ Bm, float* __restrict__ C,
    int M, int K,
    const float* __restrict__ sc, const float* __restrict__ sh,
    const float* __restrict__ rowsum, const float* __restrict__ bias,
    float* __restrict__ statsOut, int klen) {
    constexpr int NE = N * NB;      // 64
    constexpr int TM = 16 * RM;
    __shared__ __align__(16) float As[32][TM + 8];
    __shared__ __align__(16) float Bs[32][NE];
    int t = threadIdx.x;
    int tx = t & 15, ty = t >> 4;
    int m0 = blockIdx.x * TM;
    int bgrp = blockIdx.y * NB;
    int kbase = 0, kend = K;
    if (klen > 0) {
        kbase = blockIdx.z * klen;
        kend = min(K, kbase + klen);
    }
    float acc[RM][4];
#pragma unroll
    for (int i = 0; i < RM; i++)
#pragma unroll
        for (int jj = 0; jj < 4; jj++) acc[i][jj] = 0.f;

    for (int k0 = kbase; k0 < kend; k0 += 32) {
#pragma unroll
        for (int e = 0; e < 2 * RM; e++) {
            int idx = t + e * 256;
            int row = idx >> 5, col = idx & 31;
            int m = m0 + row, k = k0 + col;
            As[col][row] = (m < M && k < kend) ? A[(size_t)m * K + k] : 0.f;
        }
#pragma unroll
        for (int e = 0; e < (32 * NE) / 256; e++) {
            int idx = t + e * 256;
            int kk = idx / NE, uu = idx % NE;
            int k = k0 + kk;
            float v = 0.f;
            if (k < kend) {
                int bb = bgrp + uu / N;
                int u = uu % N;
                v = Bm[((size_t)bb * K + k) * N + u];
                if (sc) {
                    v = fmaf(v, sc[u], sh[u]);
                    v = fmaxf(v, 0.3f * v);
                }
            }
            Bs[kk][uu] = v;
        }
        __syncthreads();
#pragma unroll 4
        for (int kk = 0; kk < 32; kk++) {
            float av[RM];
#pragma unroll
            for (int i4 = 0; i4 < RM / 4; i4++) {
                float4 a = *reinterpret_cast<const float4*>(&As[kk][ty * RM + i4 * 4]);
                av[i4 * 4 + 0] = a.x; av[i4 * 4 + 1] = a.y;
                av[i4 * 4 + 2] = a.z; av[i4 * 4 + 3] = a.w;
            }
            float4 bv = *reinterpret_cast<const float4*>(&Bs[kk][tx * 4]);
            float bw[4] = {bv.x, bv.y, bv.z, bv.w};
#pragma unroll
            for (int i = 0; i < RM; i++)
#pragma unroll
                for (int jj = 0; jj < 4; jj++)
                    acc[i][jj] = fmaf(av[i], bw[jj], acc[i][jj]);
        }
        __syncthreads();
    }

    // epilogue (+ optional fused stats partials)
    int uu0 = tx * 4;
    int bb = bgrp + uu0 / N;
    int ub = uu0 % N;
    size_t cbase = ((size_t)blockIdx.z * BB + bb) * M;
    float ps[4] = {0.f, 0.f, 0.f, 0.f}, pq[4] = {0.f, 0.f, 0.f, 0.f};
#pragma unroll
    for (int i = 0; i < RM; i++) {
        int m = m0 + ty * RM + i;
        if (m < M) {
            float rs = rowsum ? rowsum[m] : 0.f;
#pragma unroll
            for (int jj = 0; jj < 4; jj++) {
                float v = acc[i][jj];
                if (rowsum) v = fmaf(rs, bias[ub + jj], v);
                C[(cbase + m) * N + ub + jj] = v;
                ps[jj] += v;
                pq[jj] = fmaf(v, v, pq[jj]);
            }
        }
    }
    if (statsOut) {
        float* red = &As[0][0];   // reuse smem (>= 2176 floats available)
        __syncthreads();
#pragma unroll
        for (int jj = 0; jj < 4; jj++) {
            red[ty * 64 + uu0 + jj] = ps[jj];
            red[1024 + ty * 64 + uu0 + jj] = pq[jj];
        }
        __syncthreads();
        if (t < 64) {
            float s = 0.f, q = 0.f;
#pragma unroll
            for (int r = 0; r < 16; r++) {
                s += red[r * 64 + t];
                q += red[1024 + r * 64 + t];
            }
            red[2048 + t] = s;
            red[2112 + t] = q;
        }
        __syncthreads();
        if (t < N) {
            float s = 0.f, q = 0.f;
#pragma unroll
            for (int g = 0; g < NB; g++) {
                s += red[2048 + g * N + t];
                q += red[2112 + g * N + t];
            }
            int bid = blockIdx.y * gridDim.x + blockIdx.x;
            int nblk = gridDim.x * gridDim.y;
            statsOut[bid * N + t] = s;
            statsOut[nblk * N + bid * N + t] = q;
        }
    }
}

// ---------------- split-K reduce (plain, for last layer) ----------------
__global__ void k_reduce_sk(const float* __restrict__ src, float* __restrict__ dst,
                            int n, int stride) {
    int i = blockIdx.x * 256 + threadIdx.x;
    if (i >= n) return;
    float s = 0.f;
#pragma unroll
    for (int z = 0; z < SK; z++) s += src[(size_t)z * stride + i];
    dst[i] = s;
}

// ---------------- split-K reduce + channel mix fused ----------------
// dst[g][u'] = bias[u'] + sum_c (sum_z src[z][g][c]) * W[c][u']
__global__ void k_reduce_mix(const float* __restrict__ src, const float* __restrict__ W,
                             const float* __restrict__ bias, float* __restrict__ dst,
                             int rows, int Cin, int Uout, int stride) {
    __shared__ float sm[64 * 32];
    int r0 = blockIdx.x * 64;
    int t = threadIdx.x;
    int nelem = 64 * Cin;
    for (int idx = t; idx < nelem; idx += 256) {
        int r = idx / Cin, c = idx % Cin;
        int g = r0 + r;
        float s = 0.f;
        if (g < rows) {
#pragma unroll
            for (int z = 0; z < SK; z++)
                s += src[(size_t)z * stride + (size_t)g * Cin + c];
        }
        sm[r * Cin + c] = s;
    }
    __syncthreads();
    int outn = 64 * Uout;
    for (int idx = t; idx < outn; idx += 256) {
        int r = idx / Uout, u = idx % Uout;
        int g = r0 + r;
        if (g < rows) {
            float acc = bias[u];
            for (int c = 0; c < Cin; c++)
                acc = fmaf(sm[r * Cin + c], W[c * Uout + u], acc);
            dst[(size_t)g * Uout + u] = acc;
        }
    }
}

// ---------------- BN finalize over per-block partials ----------------
__global__ void k_stats_fin(int U, int nblk, const float* __restrict__ g,
                            const float* __restrict__ be) {
    int u = blockIdx.x;
    int t = threadIdx.x;
    float s = 0.f, q = 0.f;
    for (int r = t; r < nblk; r += 256) {
        s += g_part[r * U + u];
        q += g_part[nblk * U + r * U + u];
    }
    __shared__ float ss[256], qq[256];
    ss[t] = s; qq[t] = q;
    __syncthreads();
    for (int st = 128; st > 0; st >>= 1) {
        if (t < st) { ss[t] += ss[t + st]; qq[t] += qq[t + st]; }
        __syncthreads();
    }
    if (t == 0) {
        const float inv = 1.0f / (float)(BB * QQ);
        float m = ss[0] * inv;
        float var = qq[0] * inv - m * m;
        float rs = rsqrtf(var + 1e-3f);
        float scv = rs * g[u];
        g_scale[u] = scv;
        g_shift[u] = be[u] - m * scv;
    }
}

// ---------------- fused degree-norms + FC1 ----------------
__global__ void k_fc1n(const float* __restrict__ W, const float* __restrict__ bias,
                       float* __restrict__ out) {
    __shared__ float h[256];
    int b = blockIdx.x;
    int t = threadIdx.x;   // 512
    if (t < 256) {
        int blk = t >> 6;
        int u = t & 63;
        int off, sz;
        if (blk == 0)      { off = 0;  sz = 1; }
        else if (blk == 1) { off = 1;  sz = 9; }
        else if (blk == 2) { off = 10; sz = 25; }
        else               { off = 35; sz = 49; }
        const float* y = g_t3 + (size_t)b * T2D * 64;
        float s = 0.f;
        for (int r = 0; r < sz; r++) {
            float v = y[(off + r) * 64 + u];
            s = fmaf(v, v, s);
        }
        h[t] = sqrtf(s);
    }
    __syncthreads();
    float acc = bias[t];
    for (int i = 0; i < 256; i++) acc = fmaf(h[i], W[i * 512 + t], acc);
    out[b * 512 + t] = acc;
}

// ---------------- dense FC ----------------
__global__ void k_fc(const float* __restrict__ in, const float* __restrict__ W,
                     const float* __restrict__ bias, float* __restrict__ out,
                     int IN, int OUT) {
    __shared__ float s[512];
    int b = blockIdx.x;
    for (int i = threadIdx.x; i < IN; i += blockDim.x) s[i] = in[b * IN + i];
    __syncthreads();
    int j = threadIdx.x;
    if (j < OUT) {
        float acc = bias[j];
        for (int i = 0; i < IN; i++) acc = fmaf(s[i], W[i * OUT + j], acc);
        out[b * OUT + j] = acc;
    }
}

// ---------------- batch BN + ReLU, in place ----------------
__global__ void k_bnrelu(float* __restrict__ a, const float* __restrict__ g,
                         const float* __restrict__ be, int F) {
    int j = blockIdx.x;
    int b = threadIdx.x;  // 64
    float v = a[b * F + j];
    __shared__ float ss[64], qq[64];
    __shared__ float sm, sr;
    ss[b] = v; qq[b] = v * v;
    __syncthreads();
    for (int st = 32; st > 0; st >>= 1) {
        if (b < st) { ss[b] += ss[b + st]; qq[b] += qq[b + st]; }
        __syncthreads();
    }
    if (b == 0) {
        float m = ss[0] * (1.0f / 64.0f);
        float var = qq[0] * (1.0f / 64.0f) - m * m;
        sm = m;
        sr = rsqrtf(var + 1e-3f);
    }
    __syncthreads();
    float y = (v - sm) * sr * g[j] + be[j];
    a[b * F + j] = y > 0.f ? y : 0.f;
}

// ---------------- output head + softmax ----------------
__global__ void k_out(const float* __restrict__ Wout, const float* __restrict__ bout,
                      float* __restrict__ out) {
    int b = blockIdx.x;
    __shared__ float h[256];
    __shared__ float lg[40];
    for (int i = threadIdx.x; i < 256; i += 64) h[i] = g_a2[b * 256 + i];
    __syncthreads();
    if (threadIdx.x < 40) {
        float acc = bout[threadIdx.x];
        for (int i = 0; i < 256; i++) acc = fmaf(h[i], Wout[i * 40 + threadIdx.x], acc);
        lg[threadIdx.x] = acc;
    }
    __syncthreads();
    if (threadIdx.x == 0) {
        float mx = -1e30f;
        for (int i = 0; i < 40; i++) mx = fmaxf(mx, lg[i]);
        float s = 0.f;
        for (int i = 0; i < 40; i++) {
            float e = __expf(lg[i] - mx);
            lg[i] = e;
            s += e;
        }
        float inv = 1.f / s;
        for (int i = 0; i < 40; i++) out[b * 40 + i] = lg[i] * inv;
    }
}

// ---------------- launch ----------------
extern "C" void kernel_launch(void* const* d_in, const int* in_sizes, int n_in,
                              void* d_out, int out_size) {
    const float* x          = (const float*)d_in[0];
    const float* shell_dirs = (const float*)d_in[1];
    const float* A_sh       = (const float*)d_in[2];
    const float* D_eval0    = (const float*)d_in[3];
    const float* D_eval1    = (const float*)d_in[4];
    const float* D_eval2    = (const float*)d_in[5];
    const float* D_coef1    = (const float*)d_in[6];
    const float* D_coef2    = (const float*)d_in[7];
    const float* D_coefL    = (const float*)d_in[8];
    const float* W0 = (const float*)d_in[9];   const float* b0 = (const float*)d_in[10];
    const float* W1 = (const float*)d_in[11];  const float* b1 = (const float*)d_in[12];
    const float* W2 = (const float*)d_in[13];  const float* b2 = (const float*)d_in[14];
    const float* g0 = (const float*)d_in[15];  const float* be0 = (const float*)d_in[16];
    const float* g1 = (const float*)d_in[17];  const float* be1 = (const float*)d_in[18];
    const float* g2 = (const float*)d_in[19];  const float* be2 = (const float*)d_in[20];
    const float* Wfc1 = (const float*)d_in[21]; const float* bfc1 = (const float*)d_in[22];
    const float* gfc1 = (const float*)d_in[23]; const float* befc1 = (const float*)d_in[24];
    const float* Wfc2 = (const float*)d_in[25]; const float* bfc2 = (const float*)d_in[26];
    const float* gfc2 = (const float*)d_in[27]; const float* befc2 = (const float*)d_in[28];
    const float* Wout = (const float*)d_in[29]; const float* bout = (const float*)d_in[30];
    float* out = (float*)d_out;

    float *pE0, *prs0, *psh, *pz0, *pY, *pz1, *pz2, *pt3, *pck,
          *ppart, *psc, *pshf, *pa1, *pa2;
    cudaGetSymbolAddress((void**)&pE0, g_E0);
    cudaGetSymbolAddress((void**)&prs0, g_rs0);
    cudaGetSymbolAddress((void**)&psh, g_sh);
    cudaGetSymbolAddress((void**)&pz0, g_z0);
    cudaGetSymbolAddress((void**)&pY, g_Y);
    cudaGetSymbolAddress((void**)&pz1, g_z1);
    cudaGetSymbolAddress((void**)&pz2, g_z2);
    cudaGetSymbolAddress((void**)&pt3, g_t3);
    cudaGetSymbolAddress((void**)&pck, g_ck);
    cudaGetSymbolAddress((void**)&ppart, g_part);
    cudaGetSymbolAddress((void**)&psc, g_scale);
    cudaGetSymbolAddress((void**)&pshf, g_shift);
    cudaGetSymbolAddress((void**)&pa1, g_a1);
    cudaGetSymbolAddress((void**)&pa2, g_a2);

    // shell embedding
    k_prep_e0<<<516, 256>>>(x, D_eval0);
    k_shell<<<dim3(6, BB), 256>>>(shell_dirs);
    k_shproj<<<864, 256>>>(A_sh);

    // layer 0
    k_mix<<<(BB * NSH * 16 + 255) / 256, 256>>>(psh, W0, pz0, NSH, 3, 16);
    k_gemm2<16, 4, 4><<<dim3(16, 16), 256>>>(pE0, pz0, pY, QQ, NSH, nullptr, nullptr,
                                             prs0, b0, ppart, 0);
    k_stats_fin<<<16, 256>>>(16, 256, g0, be0);
    k_gemm2<16, 4, 4><<<dim3(3, 16, SK), 256>>>(D_coef1, pY, pck, T1D, QQ, psc, pshf,
                                                nullptr, nullptr, nullptr, QQ / SK);
    k_reduce_mix<<<(BB * T1D + 63) / 64, 256>>>(pck, W1, b1, pz1,
                                                BB * T1D, 16, 32, BB * T1D * 16);

    // layer 1
    k_gemm2<32, 2, 8><<<dim3(8, 32), 256>>>(D_eval1, pz1, pY, QQ, T1D, nullptr, nullptr,
                                            nullptr, nullptr, ppart, 0);
    k_stats_fin<<<32, 256>>>(32, 256, g1, be1);
    k_gemm2<32, 2, 4><<<dim3(2, 32, SK), 256>>>(D_coef2, pY, pck, T2D, QQ, psc, pshf,
                                                nullptr, nullptr, nullptr, QQ / SK);
    k_reduce_mix<<<(BB * T2D + 63) / 64, 256>>>(pck, W2, b2, pz2,
                                                BB * T2D, 32, 64, BB * T2D * 32);

    // layer 2
    k_gemm2<64, 1, 8><<<dim3(8, 64), 256>>>(D_eval2, pz2, pY, QQ, T2D, nullptr, nullptr,
                                            nullptr, nullptr, ppart, 0);
    k_stats_fin<<<64, 256>>>(64, 512, g2, be2);
    k_gemm2<64, 1, 4><<<dim3(2, 64, SK), 256>>>(D_coefL, pY, pck, T2D, QQ, psc, pshf,
                                                nullptr, nullptr, nullptr, QQ / SK);
    k_reduce_sk<<<(BB * T2D * 64 + 255) / 256, 256>>>(pck, pt3, BB * T2D * 64, BB * T2D * 64);

    // head
    k_fc1n<<<BB, 512>>>(Wfc1, bfc1, pa1);
    k_bnrelu<<<512, 64>>>(pa1, gfc1, befc1, 512);
    k_fc<<<BB, 256>>>(pa1, Wfc2, bfc2, pa2, 512, 256);
    k_bnrelu<<<256, 64>>>(pa2, gfc2, befc2, 256);
    k_out<<<BB, 64>>>(Wout, bout, out);
}